// round 5
// baseline (speedup 1.0000x reference)
#include <cuda_runtime.h>
#include <math.h>
#include <stdint.h>

// Problem dims
#define T_ 1024
#define B_ 256
#define D_ 256
#define H_ 512
#define O_ 256

#define NBLK_A 128
#define NGRP 8

typedef unsigned long long ull;

// Hidden-state history (T, B, H) — h contiguous
__device__ float g_H[(size_t)T_ * B_ * H_];
__device__ float g_h0t[B_ * H_];      // h0 transposed to (B, H)

// Tree barrier (monotone generation -> graph-replay safe)
__device__ unsigned g_cnt[NGRP];
__device__ unsigned g_root;
__device__ volatile unsigned g_gen;

// ---- packed fp32 FMA: d.lo += a.lo*b.lo ; d.hi += a.hi*b.hi (exact fp32) ----
__device__ __forceinline__ void fma2(ull& d, ull a, ull b) {
    asm("fma.rn.f32x2 %0, %1, %2, %0;" : "+l"(d) : "l"(a), "l"(b));
}
__device__ __forceinline__ float pair_sum(ull v) {
    return __uint_as_float((unsigned)(v & 0xffffffffull)) +
           __uint_as_float((unsigned)(v >> 32));
}

__device__ __forceinline__ unsigned smem_u32(const void* p) {
    return (unsigned)__cvta_generic_to_shared(p);
}
__device__ __forceinline__ void cp16(unsigned dst, const void* src) {
    asm volatile("cp.async.cg.shared.global [%0], [%1], 16;\n" ::"r"(dst), "l"(src));
}
__device__ __forceinline__ void cp_commit() {
    asm volatile("cp.async.commit_group;\n");
}
template <int N> __device__ __forceinline__ void cp_wait() {
    asm volatile("cp.async.wait_group %0;\n" ::"n"(N));
}

__device__ __forceinline__ void grid_barrier(int bid) {
    __threadfence();
    __syncthreads();
    if (threadIdx.x == 0) {
        unsigned my = g_gen;
        if (atomicAdd(&g_cnt[bid & (NGRP - 1)], 1u) == (NBLK_A / NGRP - 1u)) {
            if (atomicAdd(&g_root, 1u) == NGRP - 1u) {
                atomicExch(&g_root, 0u);
                #pragma unroll
                for (int i = 0; i < NGRP; ++i) atomicExch(&g_cnt[i], 0u);
                __threadfence();
                g_gen = my + 1u;
            }
        }
        while (g_gen == my) { }
    }
    __syncthreads();
    __threadfence();
}

// Prep: h0 (H,B) -> (B,H)
__global__ void prep_h0t(const float* __restrict__ h0) {
    int b = blockIdx.x;               // 256
    int h = threadIdx.x;              // 512
    g_h0t[(size_t)b * H_ + h] = h0[(size_t)h * B_ + b];
}

// ---------------------------------------------------------------------------
// Phase A: h_t = tanh(U[:,x_t] + W h_{t-1} + bh). 128 CTAs x 128 threads.
// Tile 32h x 32b; thread = 2h x 4b; k-split f32x2 accumulators.
// Ws[32][512] XOR-swizzled; Hs[32][516] (k contiguous).
// ---------------------------------------------------------------------------
#define HS_STRIDE 516
#define SMEM_A_WORDS (32 * 512 + 32 * HS_STRIDE)

__global__ void __launch_bounds__(128, 1)
rnn_recur_kernel(const int* __restrict__ inp, const float* __restrict__ U,
                 const float* __restrict__ W, const float* __restrict__ bh)
{
    extern __shared__ float smem[];
    float* Ws = smem;                   // 32*512
    float* Hs = smem + 32 * 512;        // 32*516

    const int bid = blockIdx.x;
    const int br = bid >> 3, bc = bid & 7;
    const int r0 = br * 32, c0 = bc * 32;
    const int tid = threadIdx.x;
    const int tx = tid & 15;            // rows 2tx, 2tx+1
    const int ty = tid >> 4;            // cols 4ty .. 4ty+3
    const int row  = r0 + 2 * tx;
    const int colb = c0 + 4 * ty;

    // Load W slab (32 x 512) once, 16B-chunk XOR swizzle per row-pair
    for (int i = tid; i < 4096; i += 128) {
        int r  = i >> 7;
        int k4 = (i & 127) << 2;
        float4 w = *(const float4*)&W[(size_t)(r0 + r) * H_ + k4];
        int o = k4 ^ (((r >> 1) & 7) << 2);
        *(float4*)&Ws[r * 512 + o] = w;
    }
    const float b0 = bh[row];
    const float b1 = bh[row + 1];

    const float* w0p = Ws + (2 * tx) * 512;
    const float* w1p = w0p + 512;
    const int    sx  = (tx & 7) << 2;
    const float* hp  = Hs + (4 * ty) * HS_STRIDE;
    const unsigned sbase = smem_u32(Hs);

    __syncthreads();

    const float* hprev = g_h0t;
    float*       hdst  = g_H;

    for (int t = 0; t < T_; ++t) {
        // Async slab fill (64 KB), two k-halves for load/compute overlap
        #pragma unroll
        for (int j = 0; j < 16; ++j) {
            int i   = tid + j * 128;          // 0..2047
            int col = i >> 6;
            int k4  = (i & 63) << 2;          // k in [0,256)
            cp16(sbase + (unsigned)((col * HS_STRIDE + k4) << 2),
                 hprev + (size_t)(c0 + col) * H_ + k4);
        }
        cp_commit();
        #pragma unroll
        for (int j = 0; j < 16; ++j) {
            int i   = tid + j * 128;
            int col = i >> 6;
            int k4  = ((i & 63) << 2) + 256;  // k in [256,512)
            cp16(sbase + (unsigned)((col * HS_STRIDE + k4) << 2),
                 hprev + (size_t)(c0 + col) * H_ + k4);
        }
        cp_commit();

        // U column-gather + bias (overlaps cp.async)
        int xs[4];
        #pragma unroll
        for (int c = 0; c < 4; ++c) xs[c] = inp[t * B_ + colb + c];
        float u0[4], u1[4];
        #pragma unroll
        for (int c = 0; c < 4; ++c) {
            u0[c] = U[(size_t)row * D_ + xs[c]];
            u1[c] = U[(size_t)(row + 1) * D_ + xs[c]];
        }

        ull a0[4] = {0, 0, 0, 0};   // row 2tx,   cols c: (even-k, odd-k) partials
        ull a1[4] = {0, 0, 0, 0};   // row 2tx+1

        cp_wait<1>();
        __syncthreads();
        #pragma unroll 4
        for (int k4 = 0; k4 < 256; k4 += 4) {
            int o = k4 ^ sx;
            ulonglong2 wa = *(const ulonglong2*)(w0p + o);
            ulonglong2 wb = *(const ulonglong2*)(w1p + o);
            #pragma unroll
            for (int c = 0; c < 4; ++c) {
                ulonglong2 hc = *(const ulonglong2*)(hp + c * HS_STRIDE + k4);
                fma2(a0[c], wa.x, hc.x);
                fma2(a1[c], wb.x, hc.x);
                fma2(a0[c], wa.y, hc.y);
                fma2(a1[c], wb.y, hc.y);
            }
        }
        cp_wait<0>();
        __syncthreads();
        #pragma unroll 4
        for (int k4 = 256; k4 < 512; k4 += 4) {
            int o = k4 ^ sx;
            ulonglong2 wa = *(const ulonglong2*)(w0p + o);
            ulonglong2 wb = *(const ulonglong2*)(w1p + o);
            #pragma unroll
            for (int c = 0; c < 4; ++c) {
                ulonglong2 hc = *(const ulonglong2*)(hp + c * HS_STRIDE + k4);
                fma2(a0[c], wa.x, hc.x);
                fma2(a1[c], wb.x, hc.x);
                fma2(a0[c], wa.y, hc.y);
                fma2(a1[c], wb.y, hc.y);
            }
        }

        // Combine partials, tanh, store to (B,H)
        #pragma unroll
        for (int c = 0; c < 4; ++c) {
            float h0v = tanhf(pair_sum(a0[c]) + u0[c] + b0);
            float h1v = tanhf(pair_sum(a1[c]) + u1[c] + b1);
            *(float2*)&hdst[(size_t)(colb + c) * H_ + row] =
                make_float2(h0v, h1v);
        }

        hprev = hdst;
        hdst += (size_t)B_ * H_;
        grid_barrier(bid);
    }
}

// ---------------------------------------------------------------------------
// Phase B: out[t,b,o] = by[o] + sum_k g_H[t,b,k] * V[o,k]
// Tile 64b x 64o, 256 threads, thread = 4b x 4o, k-split f32x2 accumulators.
// Both operands k-contiguous in smem (no transpose); Vs XOR-swizzled.
// ---------------------------------------------------------------------------
__global__ void __launch_bounds__(256, 2)
rnn_logits_kernel(const float* __restrict__ Vm, const float* __restrict__ by,
                  float* __restrict__ out)
{
    __shared__ float As[64 * 32];    // [b][k], swizzled by ((b>>2)&7)
    __shared__ float Vs[64 * 32];    // [o][k], swizzled by ((o>>2)&7)

    const int t  = blockIdx.z;
    const int ob = blockIdx.x * 64;
    const int bb = blockIdx.y * 64;
    const int tid = threadIdx.x;
    const int tx = tid & 15;         // o rows 4tx .. 4tx+3
    const int ty = tid >> 4;         // b rows 4ty .. 4ty+3

    const float* A = g_H + (size_t)t * (B_ * H_) + (size_t)bb * H_;

    ull acc[4][4];
    #pragma unroll
    for (int m = 0; m < 4; ++m)
        #pragma unroll
        for (int n = 0; n < 4; ++n) acc[m][n] = 0ull;

    const int swA = ((ty & 1) << 4) | ((/*unused*/0));
    (void)swA;

    for (int kc = 0; kc < H_; kc += 32) {
        // Fill As: 64 rows x 32k = 512 float4, 2 per thread
        #pragma unroll
        for (int j = 0; j < 2; ++j) {
            int i  = tid + j * 256;
            int b  = i >> 3;
            int k4 = (i & 7) << 2;
            int o  = k4 ^ (((b >> 2) & 7) << 2);
            *(float4*)&As[b * 32 + o] =
                *(const float4*)&A[(size_t)b * H_ + kc + k4];
        }
        // Fill Vs: 64 rows x 32k
        #pragma unroll
        for (int j = 0; j < 2; ++j) {
            int i  = tid + j * 256;
            int o_ = i >> 3;
            int k4 = (i & 7) << 2;
            int o  = k4 ^ (((o_ >> 2) & 7) << 2);
            *(float4*)&Vs[o_ * 32 + o] =
                *(const float4*)&Vm[(size_t)(ob + o_) * H_ + kc + k4];
        }
        __syncthreads();

        const int sa = ((ty & 7) << 2);   // (4ty>>2)&7 == ty&7
        const int sv = ((tx & 7) << 2);
        #pragma unroll
        for (int k4 = 0; k4 < 32; k4 += 4) {
            ulonglong2 av[4], vv[4];
            #pragma unroll
            for (int m = 0; m < 4; ++m)
                av[m] = *(const ulonglong2*)&As[(4 * ty + m) * 32 + (k4 ^ sa)];
            #pragma unroll
            for (int n = 0; n < 4; ++n)
                vv[n] = *(const ulonglong2*)&Vs[(4 * tx + n) * 32 + (k4 ^ sv)];
            #pragma unroll
            for (int m = 0; m < 4; ++m)
                #pragma unroll
                for (int n = 0; n < 4; ++n) {
                    fma2(acc[m][n], av[m].x, vv[n].x);
                    fma2(acc[m][n], av[m].y, vv[n].y);
                }
        }
        __syncthreads();
    }

    const float4 byv = *(const float4*)&by[ob + 4 * tx];
    #pragma unroll
    for (int m = 0; m < 4; ++m) {
        float4 r = make_float4(pair_sum(acc[m][0]) + byv.x,
                               pair_sum(acc[m][1]) + byv.y,
                               pair_sum(acc[m][2]) + byv.z,
                               pair_sum(acc[m][3]) + byv.w);
        *(float4*)&out[((size_t)t * B_ + bb + 4 * ty + m) * O_ + ob + 4 * tx] = r;
    }
}

// Optional hT (H,B) appended after logits
__global__ void copy_hT_kernel(float* __restrict__ out) {
    int h = blockIdx.x;      // 512
    int b = threadIdx.x;     // 256
    out[(size_t)h * B_ + b] =
        g_H[(size_t)(T_ - 1) * (B_ * H_) + (size_t)b * H_ + h];
}

extern "C" void kernel_launch(void* const* d_in, const int* in_sizes, int n_in,
                              void* d_out, int out_size) {
    const int*   inp = (const int*)d_in[0];
    const float* h0  = (const float*)d_in[1];
    const float* U   = (const float*)d_in[2];
    const float* W   = (const float*)d_in[3];
    const float* Vm  = (const float*)d_in[4];
    const float* bh  = (const float*)d_in[5];
    const float* by  = (const float*)d_in[6];
    float* out = (float*)d_out;

    cudaFuncSetAttribute(rnn_recur_kernel,
                         cudaFuncAttributeMaxDynamicSharedMemorySize,
                         (int)(SMEM_A_WORDS * sizeof(float)));

    prep_h0t<<<B_, H_>>>(h0);

    rnn_recur_kernel<<<NBLK_A, 128, SMEM_A_WORDS * sizeof(float)>>>(inp, U, W, bh);

    dim3 gridB(O_ / 64, B_ / 64, T_);
    rnn_logits_kernel<<<gridB, 256>>>(Vm, by, out);

    if (out_size >= T_ * B_ * O_ + H_ * B_) {
        copy_hT_kernel<<<H_, B_>>>(out + (size_t)T_ * B_ * O_);
    }
}

// round 7
// speedup vs baseline: 1.5445x; 1.5445x over previous
#include <cuda_runtime.h>
#include <cuda_bf16.h>
#include <math.h>
#include <stdint.h>

// Problem dims
#define T_ 1024
#define B_ 256
#define D_ 256
#define H_ 512
#define O_ 256

// Phase A: 128 CTAs, tile 32h x 32b (16 row-blocks x 8 col-blocks), 4 warps k-split
#define NBLK_A 128
#define NGRP 8
#define MB 32
#define NB 32

typedef unsigned long long ull;

// fp32 hidden history (Phase B + hT) and bf16 hi/lo planes, (b, h) layout
__device__ float          g_H  [(size_t)T_ * B_ * H_];
__device__ unsigned short g_Hhi[(size_t)T_ * B_ * H_];
__device__ unsigned short g_Hlo[(size_t)T_ * B_ * H_];
__device__ unsigned short g_h0hi[B_ * H_];
__device__ unsigned short g_h0lo[B_ * H_];
__device__ float          g_Ut[D_ * H_];      // U transposed (D, H)

// Tree barrier (monotone generation -> graph-replay safe)
__device__ unsigned g_cnt[NGRP];
__device__ unsigned g_root;
__device__ volatile unsigned g_gen;

// ---------------- helpers ----------------
__device__ __forceinline__ void fma2(ull& d, ull a, ull b) {
    asm("fma.rn.f32x2 %0, %1, %2, %0;" : "+l"(d) : "l"(a), "l"(b));
}
__device__ __forceinline__ float pair_sum(ull v) {
    return __uint_as_float((unsigned)(v & 0xffffffffull)) +
           __uint_as_float((unsigned)(v >> 32));
}
__device__ __forceinline__ unsigned smem_u32(const void* p) {
    return (unsigned)__cvta_generic_to_shared(p);
}
__device__ __forceinline__ void cp16(unsigned dst, const void* src) {
    asm volatile("cp.async.cg.shared.global [%0], [%1], 16;\n" ::"r"(dst), "l"(src));
}
__device__ __forceinline__ void cp_commit() {
    asm volatile("cp.async.commit_group;\n");
}
template <int N> __device__ __forceinline__ void cp_wait() {
    asm volatile("cp.async.wait_group %0;\n" ::"n"(N));
}
__device__ __forceinline__ float fast_tanh(float x) {
    float e, r;
    asm("ex2.approx.f32 %0, %1;" : "=f"(e) : "f"(x * 2.8853900817779268f));
    asm("rcp.approx.f32 %0, %1;" : "=f"(r) : "f"(e + 1.0f));
    return fmaf(-2.0f, r, 1.0f);
}
__device__ __forceinline__ void ldsm_x4(unsigned* r, unsigned addr) {
    asm volatile("ldmatrix.sync.aligned.m8n8.x4.shared.b16 {%0,%1,%2,%3}, [%4];"
                 : "=r"(r[0]), "=r"(r[1]), "=r"(r[2]), "=r"(r[3]) : "r"(addr));
}
__device__ __forceinline__ void ldsm_x2(unsigned* r, unsigned addr) {
    asm volatile("ldmatrix.sync.aligned.m8n8.x2.shared.b16 {%0,%1}, [%2];"
                 : "=r"(r[0]), "=r"(r[1]) : "r"(addr));
}
// D(16x8,f32) += A(16x16,bf16,row) * B(16x8,bf16,col)
__device__ __forceinline__ void mma_bf16(float* d, const unsigned* a, const unsigned* b) {
    asm volatile(
        "mma.sync.aligned.m16n8k16.row.col.f32.bf16.bf16.f32 "
        "{%0,%1,%2,%3}, {%4,%5,%6,%7}, {%8,%9}, {%0,%1,%2,%3};"
        : "+f"(d[0]), "+f"(d[1]), "+f"(d[2]), "+f"(d[3])
        : "r"(a[0]), "r"(a[1]), "r"(a[2]), "r"(a[3]), "r"(b[0]), "r"(b[1]));
}

__device__ __forceinline__ void grid_barrier(int bid) {
    __threadfence();
    __syncthreads();
    if (threadIdx.x == 0) {
        unsigned my = g_gen;
        if (atomicAdd(&g_cnt[bid & (NGRP - 1)], 1u) == (NBLK_A / NGRP - 1u)) {
            if (atomicAdd(&g_root, 1u) == NGRP - 1u) {
                atomicExch(&g_root, 0u);
                #pragma unroll
                for (int i = 0; i < NGRP; ++i) atomicExch(&g_cnt[i], 0u);
                __threadfence();
                g_gen = my + 1u;
            }
        }
        while (g_gen == my) { }
    }
    __syncthreads();
    __threadfence();
}

// ---------------- prep kernels ----------------
__global__ void prep_Ut(const float* __restrict__ U) {
    int d = blockIdx.x, h = threadIdx.x;
    g_Ut[(size_t)d * H_ + h] = U[(size_t)h * D_ + d];
}
__global__ void prep_h0planes(const float* __restrict__ h0) {
    int b = blockIdx.x, h = threadIdx.x;
    float v = h0[(size_t)h * B_ + b];
    __nv_bfloat16 hi = __float2bfloat16_rn(v);
    __nv_bfloat16 lo = __float2bfloat16_rn(v - __bfloat162float(hi));
    g_h0hi[(size_t)b * H_ + h] = __bfloat16_as_ushort(hi);
    g_h0lo[(size_t)b * H_ + h] = __bfloat16_as_ushort(lo);
}

// ---------------- Phase A: warp-MMA recurrence ----------------
// smem bytes: Wh[32][512]bf16 | Wl | Hh[32][512]bf16 | Hl | RED f32[4][32][33]
// all [row][k] with 16B-chunk swizzle: chunk' = (k>>3) ^ (row&7)
#define WH_OFF 0
#define WL_OFF 32768
#define HH_OFF 65536
#define HL_OFF 98304
#define RED_OFF 131072
#define SMEM_A_BYTES (RED_OFF + 4 * 32 * 33 * 4)

__global__ void __launch_bounds__(128, 1)
rnn_recur_mma(const int* __restrict__ inp, const float* __restrict__ W,
              const float* __restrict__ bh)
{
    extern __shared__ char smem[];
    const unsigned sb = smem_u32(smem);
    float* RED = (float*)(smem + RED_OFF);

    const int tid = threadIdx.x;
    const int w   = tid >> 5;
    const int l   = tid & 31;
    const int bid = blockIdx.x;
    const int r0 = (bid >> 3) * MB;     // h-rows
    const int c0 = (bid & 7) * NB;      // b-cols

    // ---- one-time: split W slab (32 x 512) into Wh/Wl bf16, swizzled smem
    for (int i = tid; i < MB * H_; i += 128) {
        int row = i >> 9, k = i & 511;
        float wv = W[(size_t)(r0 + row) * H_ + k];
        __nv_bfloat16 hi = __float2bfloat16_rn(wv);
        __nv_bfloat16 lo = __float2bfloat16_rn(wv - __bfloat162float(hi));
        unsigned off = (unsigned)row * 1024u +
                       ((((unsigned)k >> 3) ^ (unsigned)(row & 7)) << 4) +
                       (unsigned)(k & 7) * 2u;
        *(__nv_bfloat16*)(smem + WH_OFF + off) = hi;
        *(__nv_bfloat16*)(smem + WL_OFF + off) = lo;
    }

    // epilogue ownership: thread -> col en (0..31), rows em..em+7
    const int en = tid >> 2;
    const int em = (tid & 3) * 8;
    float bhv[8];
    *(float4*)&bhv[0] = *(const float4*)&bh[r0 + em];
    *(float4*)&bhv[4] = *(const float4*)&bh[r0 + em + 4];
    __syncthreads();

    // ldmatrix lane geometry
    const int kw    = w * 128;               // this warp's k quarter
    const int quad  = l >> 3, li = l & 7;
    const int a_row = ((quad & 1) << 3) + li;         // + mt*16
    const int a_kof = (quad >> 1) << 3;
    const int b_i   = l & 7;
    const int b_half = (l >> 3) & 1;

    for (int t = 0; t < T_; ++t) {
        // ---- fill h planes (b-slice, bf16 hi/lo), hh first for overlap
        const unsigned short* sHi =
            (t == 0) ? g_h0hi : g_Hhi + (size_t)(t - 1) * B_ * H_;
        const unsigned short* sLo =
            (t == 0) ? g_h0lo : g_Hlo + (size_t)(t - 1) * B_ * H_;
        #pragma unroll
        for (int j = 0; j < 16; ++j) {
            int i = tid + j * 128;               // 0..2047
            int row = i >> 6, c = i & 63;
            cp16(sb + HH_OFF + (unsigned)row * 1024u + ((unsigned)(c ^ (row & 7)) << 4),
                 sHi + (size_t)(c0 + row) * H_ + c * 8);
        }
        cp_commit();
        #pragma unroll
        for (int j = 0; j < 16; ++j) {
            int i = tid + j * 128;
            int row = i >> 6, c = i & 63;
            cp16(sb + HL_OFF + (unsigned)row * 1024u + ((unsigned)(c ^ (row & 7)) << 4),
                 sLo + (size_t)(c0 + row) * H_ + c * 8);
        }
        cp_commit();

        // ---- U gather (overlaps cp.async)
        int x = inp[t * B_ + c0 + en];
        float uv[8];
        *(float4*)&uv[0] = *(const float4*)&g_Ut[(size_t)x * H_ + r0 + em];
        *(float4*)&uv[4] = *(const float4*)&g_Ut[(size_t)x * H_ + r0 + em + 4];

        float acc[2][4][4];
        #pragma unroll
        for (int mt = 0; mt < 2; ++mt)
            #pragma unroll
            for (int nt = 0; nt < 4; ++nt)
                #pragma unroll
                for (int q = 0; q < 4; ++q) acc[mt][nt][q] = 0.f;

        cp_wait<1>();
        __syncthreads();

        // ---- phase 1: Wh*hh + Wl*hh over this warp's k quarter
        #pragma unroll
        for (int ks = 0; ks < 8; ++ks) {
            const int kk = kw + ks * 16;
            unsigned bfr[4][2];
            #pragma unroll
            for (int nt = 0; nt < 4; ++nt) {
                int rn = nt * 8 + b_i;
                unsigned ba = sb + HH_OFF + (unsigned)rn * 1024u +
                    ((((unsigned)(kk + b_half * 8) >> 3) ^ (unsigned)(rn & 7)) << 4);
                ldsm_x2(bfr[nt], ba);
            }
            #pragma unroll
            for (int mt = 0; mt < 2; ++mt) {
                int row = mt * 16 + a_row;
                unsigned afr[4];
                unsigned aa = sb + WH_OFF + (unsigned)row * 1024u +
                    ((((unsigned)(kk + a_kof) >> 3) ^ (unsigned)(row & 7)) << 4);
                ldsm_x4(afr, aa);
                #pragma unroll
                for (int nt = 0; nt < 4; ++nt) mma_bf16(acc[mt][nt], afr, bfr[nt]);
            }
            #pragma unroll
            for (int mt = 0; mt < 2; ++mt) {
                int row = mt * 16 + a_row;
                unsigned afr[4];
                unsigned aa = sb + WL_OFF + (unsigned)row * 1024u +
                    ((((unsigned)(kk + a_kof) >> 3) ^ (unsigned)(row & 7)) << 4);
                ldsm_x4(afr, aa);
                #pragma unroll
                for (int nt = 0; nt < 4; ++nt) mma_bf16(acc[mt][nt], afr, bfr[nt]);
            }
        }

        cp_wait<0>();
        __syncthreads();

        // ---- phase 2: Wh*hl
        #pragma unroll
        for (int ks = 0; ks < 8; ++ks) {
            const int kk = kw + ks * 16;
            unsigned bfr[4][2];
            #pragma unroll
            for (int nt = 0; nt < 4; ++nt) {
                int rn = nt * 8 + b_i;
                unsigned ba = sb + HL_OFF + (unsigned)rn * 1024u +
                    ((((unsigned)(kk + b_half * 8) >> 3) ^ (unsigned)(rn & 7)) << 4);
                ldsm_x2(bfr[nt], ba);
            }
            #pragma unroll
            for (int mt = 0; mt < 2; ++mt) {
                int row = mt * 16 + a_row;
                unsigned afr[4];
                unsigned aa = sb + WH_OFF + (unsigned)row * 1024u +
                    ((((unsigned)(kk + a_kof) >> 3) ^ (unsigned)(row & 7)) << 4);
                ldsm_x4(afr, aa);
                #pragma unroll
                for (int nt = 0; nt < 4; ++nt) mma_bf16(acc[mt][nt], afr, bfr[nt]);
            }
        }

        // ---- cross-warp k reduction via smem
        {
            int g = l >> 2, q = l & 3;
            #pragma unroll
            for (int mt = 0; mt < 2; ++mt)
                #pragma unroll
                for (int nt = 0; nt < 4; ++nt) {
                    int m = mt * 16 + g, n = nt * 8 + 2 * q;
                    RED[(w * 32 + m) * 33 + n]         = acc[mt][nt][0];
                    RED[(w * 32 + m) * 33 + n + 1]     = acc[mt][nt][1];
                    RED[(w * 32 + m + 8) * 33 + n]     = acc[mt][nt][2];
                    RED[(w * 32 + m + 8) * 33 + n + 1] = acc[mt][nt][3];
                }
        }
        __syncthreads();

        // ---- epilogue: sum partials + U + bias, tanh, store fp32 + planes
        float* gH = g_H + (size_t)t * B_ * H_;
        unsigned short* pHi = g_Hhi + (size_t)t * B_ * H_;
        unsigned short* pLo = g_Hlo + (size_t)t * B_ * H_;
        float hv[8];
        #pragma unroll
        for (int r = 0; r < 8; ++r) {
            int m = em + r;
            float s = RED[(0 * 32 + m) * 33 + en] + RED[(1 * 32 + m) * 33 + en] +
                      RED[(2 * 32 + m) * 33 + en] + RED[(3 * 32 + m) * 33 + en];
            hv[r] = fast_tanh(s + uv[r] + bhv[r]);
        }
        size_t ofs = (size_t)(c0 + en) * H_ + r0 + em;
        *(float4*)&gH[ofs]     = *(float4*)&hv[0];
        *(float4*)&gH[ofs + 4] = *(float4*)&hv[4];
        unsigned short hu[8], lu[8];
        #pragma unroll
        for (int r = 0; r < 8; ++r) {
            __nv_bfloat16 hi = __float2bfloat16_rn(hv[r]);
            __nv_bfloat16 lo = __float2bfloat16_rn(hv[r] - __bfloat162float(hi));
            hu[r] = __bfloat16_as_ushort(hi);
            lu[r] = __bfloat16_as_ushort(lo);
        }
        *(uint4*)&pHi[ofs] = *(uint4*)&hu[0];
        *(uint4*)&pLo[ofs] = *(uint4*)&lu[0];

        grid_barrier(bid);
    }
}

// ---------------- Phase B: logits GEMM (proven f32x2 version) ----------------
__global__ void __launch_bounds__(256, 2)
rnn_logits_kernel(const float* __restrict__ Vm, const float* __restrict__ by,
                  float* __restrict__ out)
{
    __shared__ float As[64 * 32];
    __shared__ float Vs[64 * 32];

    const int t  = blockIdx.z;
    const int ob = blockIdx.x * 64;
    const int bb = blockIdx.y * 64;
    const int tid = threadIdx.x;
    const int tx = tid & 15;
    const int ty = tid >> 4;

    const float* A = g_H + (size_t)t * (B_ * H_) + (size_t)bb * H_;

    ull acc[4][4];
    #pragma unroll
    for (int m = 0; m < 4; ++m)
        #pragma unroll
        for (int n = 0; n < 4; ++n) acc[m][n] = 0ull;

    for (int kc = 0; kc < H_; kc += 32) {
        #pragma unroll
        for (int j = 0; j < 2; ++j) {
            int i  = tid + j * 256;
            int b  = i >> 3;
            int k4 = (i & 7) << 2;
            int o  = k4 ^ (((b >> 2) & 7) << 2);
            *(float4*)&As[b * 32 + o] =
                *(const float4*)&A[(size_t)b * H_ + kc + k4];
        }
        #pragma unroll
        for (int j = 0; j < 2; ++j) {
            int i  = tid + j * 256;
            int o_ = i >> 3;
            int k4 = (i & 7) << 2;
            int o  = k4 ^ (((o_ >> 2) & 7) << 2);
            *(float4*)&Vs[o_ * 32 + o] =
                *(const float4*)&Vm[(size_t)(ob + o_) * H_ + kc + k4];
        }
        __syncthreads();

        const int sa = ((ty & 7) << 2);
        const int sv = ((tx & 7) << 2);
        #pragma unroll
        for (int k4 = 0; k4 < 32; k4 += 4) {
            ulonglong2 av[4], vv[4];
            #pragma unroll
            for (int m = 0; m < 4; ++m)
                av[m] = *(const ulonglong2*)&As[(4 * ty + m) * 32 + (k4 ^ sa)];
            #pragma unroll
            for (int n = 0; n < 4; ++n)
                vv[n] = *(const ulonglong2*)&Vs[(4 * tx + n) * 32 + (k4 ^ sv)];
            #pragma unroll
            for (int m = 0; m < 4; ++m)
                #pragma unroll
                for (int n = 0; n < 4; ++n) {
                    fma2(acc[m][n], av[m].x, vv[n].x);
                    fma2(acc[m][n], av[m].y, vv[n].y);
                }
        }
        __syncthreads();
    }

    const float4 byv = *(const float4*)&by[ob + 4 * tx];
    #pragma unroll
    for (int m = 0; m < 4; ++m) {
        float4 r = make_float4(pair_sum(acc[m][0]) + byv.x,
                               pair_sum(acc[m][1]) + byv.y,
                               pair_sum(acc[m][2]) + byv.z,
                               pair_sum(acc[m][3]) + byv.w);
        *(float4*)&out[((size_t)t * B_ + bb + 4 * ty + m) * O_ + ob + 4 * tx] = r;
    }
}

// Optional hT (H,B) appended after logits
__global__ void copy_hT_kernel(float* __restrict__ out) {
    int h = blockIdx.x;      // 512
    int b = threadIdx.x;     // 256
    out[(size_t)h * B_ + b] =
        g_H[(size_t)(T_ - 1) * (B_ * H_) + (size_t)b * H_ + h];
}

extern "C" void kernel_launch(void* const* d_in, const int* in_sizes, int n_in,
                              void* d_out, int out_size) {
    const int*   inp = (const int*)d_in[0];
    const float* h0  = (const float*)d_in[1];
    const float* U   = (const float*)d_in[2];
    const float* W   = (const float*)d_in[3];
    const float* Vm  = (const float*)d_in[4];
    const float* bh  = (const float*)d_in[5];
    const float* by  = (const float*)d_in[6];
    float* out = (float*)d_out;

    cudaFuncSetAttribute(rnn_recur_mma,
                         cudaFuncAttributeMaxDynamicSharedMemorySize,
                         (int)SMEM_A_BYTES);

    prep_Ut<<<D_, H_>>>(U);
    prep_h0planes<<<B_, H_>>>(h0);

    rnn_recur_mma<<<NBLK_A, 128, SMEM_A_BYTES>>>(inp, W, bh);

    dim3 gridB(O_ / 64, B_ / 64, T_);
    rnn_logits_kernel<<<gridB, 256>>>(Vm, by, out);

    if (out_size >= T_ * B_ * O_ + H_ * B_) {
        copy_hT_kernel<<<H_, B_>>>(out + (size_t)T_ * B_ * O_);
    }
}

// round 8
// speedup vs baseline: 2.1481x; 1.3908x over previous
#include <cuda_runtime.h>
#include <cuda_bf16.h>
#include <math.h>
#include <stdint.h>

// Problem dims
#define T_ 1024
#define B_ 256
#define D_ 256
#define H_ 512
#define O_ 256

#define NBLK_A 128
#define MB 32
#define NB 32

typedef unsigned long long ull;

// bf16 hi/lo planes of hidden history, (t, b, h) layout, h contiguous
__device__ unsigned short g_Hhi[(size_t)T_ * B_ * H_];
__device__ unsigned short g_Hlo[(size_t)T_ * B_ * H_];
__device__ unsigned short g_h0hi[B_ * H_];
__device__ unsigned short g_h0lo[B_ * H_];
__device__ unsigned short g_Vhi[O_ * H_];
__device__ unsigned short g_Vlo[O_ * H_];
__device__ float          g_Ut[D_ * H_];      // U transposed (D, H)

// Per-column-group barriers (8 groups x 16 CTAs), one cache line each
__device__ unsigned g_cg_cnt[8 * 32];
__device__ volatile unsigned g_cg_gen[8 * 32];

// ---------------- helpers ----------------
__device__ __forceinline__ float bf16hl(unsigned short u) {
    return __uint_as_float((unsigned)u << 16);
}
__device__ __forceinline__ unsigned smem_u32(const void* p) {
    return (unsigned)__cvta_generic_to_shared(p);
}
__device__ __forceinline__ void cp16(unsigned dst, const void* src) {
    asm volatile("cp.async.cg.shared.global [%0], [%1], 16;\n" ::"r"(dst), "l"(src));
}
__device__ __forceinline__ void cp_commit() {
    asm volatile("cp.async.commit_group;\n");
}
template <int N> __device__ __forceinline__ void cp_wait() {
    asm volatile("cp.async.wait_group %0;\n" ::"n"(N));
}
__device__ __forceinline__ float fast_tanh(float x) {
    float e, r;
    asm("ex2.approx.f32 %0, %1;" : "=f"(e) : "f"(x * 2.8853900817779268f));
    asm("rcp.approx.f32 %0, %1;" : "=f"(r) : "f"(e + 1.0f));
    return fmaf(-2.0f, r, 1.0f);
}
__device__ __forceinline__ void ldsm_x4(unsigned* r, unsigned addr) {
    asm volatile("ldmatrix.sync.aligned.m8n8.x4.shared.b16 {%0,%1,%2,%3}, [%4];"
                 : "=r"(r[0]), "=r"(r[1]), "=r"(r[2]), "=r"(r[3]) : "r"(addr));
}
__device__ __forceinline__ void ldsm_x2(unsigned* r, unsigned addr) {
    asm volatile("ldmatrix.sync.aligned.m8n8.x2.shared.b16 {%0,%1}, [%2];"
                 : "=r"(r[0]), "=r"(r[1]) : "r"(addr));
}
__device__ __forceinline__ void mma_bf16(float* d, const unsigned* a, const unsigned* b) {
    asm volatile(
        "mma.sync.aligned.m16n8k16.row.col.f32.bf16.bf16.f32 "
        "{%0,%1,%2,%3}, {%4,%5,%6,%7}, {%8,%9}, {%0,%1,%2,%3};"
        : "+f"(d[0]), "+f"(d[1]), "+f"(d[2]), "+f"(d[3])
        : "r"(a[0]), "r"(a[1]), "r"(a[2]), "r"(a[3]), "r"(b[0]), "r"(b[1]));
}

// Column-group barrier: 16 CTAs sharing column block bc
__device__ __forceinline__ void group_barrier(int bc) {
    __threadfence();
    __syncthreads();
    if (threadIdx.x == 0) {
        volatile unsigned* gen = &g_cg_gen[bc * 32];
        unsigned* cnt = &g_cg_cnt[bc * 32];
        unsigned my = *gen;
        if (atomicAdd(cnt, 1u) == 15u) {
            atomicExch(cnt, 0u);
            __threadfence();
            *gen = my + 1u;
        }
        while (*gen == my) { }
    }
    __syncthreads();
    __threadfence();
}

// ---------------- prep kernels ----------------
__global__ void prep_Ut(const float* __restrict__ U) {
    int d = blockIdx.x, h = threadIdx.x;
    g_Ut[(size_t)d * H_ + h] = U[(size_t)h * D_ + d];
}
__global__ void prep_h0planes(const float* __restrict__ h0) {
    int b = blockIdx.x, h = threadIdx.x;
    float v = h0[(size_t)h * B_ + b];
    __nv_bfloat16 hi = __float2bfloat16_rn(v);
    __nv_bfloat16 lo = __float2bfloat16_rn(v - __bfloat162float(hi));
    g_h0hi[(size_t)b * H_ + h] = __bfloat16_as_ushort(hi);
    g_h0lo[(size_t)b * H_ + h] = __bfloat16_as_ushort(lo);
}
__global__ void prep_Vplanes(const float* __restrict__ Vm) {
    int o = blockIdx.x, h = threadIdx.x;
    float v = Vm[(size_t)o * H_ + h];
    __nv_bfloat16 hi = __float2bfloat16_rn(v);
    __nv_bfloat16 lo = __float2bfloat16_rn(v - __bfloat162float(hi));
    g_Vhi[(size_t)o * H_ + h] = __bfloat16_as_ushort(hi);
    g_Vlo[(size_t)o * H_ + h] = __bfloat16_as_ushort(lo);
}

// ---------------- Phase A: warp-MMA recurrence (column-group sync) ----------
#define WH_OFF 0
#define WL_OFF 32768
#define HH_OFF 65536
#define HL_OFF 98304
#define RED_OFF 131072
#define SMEM_A_BYTES (RED_OFF + 4 * 32 * 33 * 4)

__global__ void __launch_bounds__(128, 1)
rnn_recur_mma(const int* __restrict__ inp, const float* __restrict__ W,
              const float* __restrict__ bh)
{
    extern __shared__ char smem[];
    const unsigned sb = smem_u32(smem);
    float* RED = (float*)(smem + RED_OFF);

    const int tid = threadIdx.x;
    const int w   = tid >> 5;
    const int l   = tid & 31;
    const int bid = blockIdx.x;
    const int r0 = (bid >> 3) * MB;
    const int bc = bid & 7;
    const int c0 = bc * NB;

    // one-time: split W slab (32 x 512) into Wh/Wl bf16, swizzled smem
    for (int i = tid; i < MB * H_; i += 128) {
        int row = i >> 9, k = i & 511;
        float wv = W[(size_t)(r0 + row) * H_ + k];
        __nv_bfloat16 hi = __float2bfloat16_rn(wv);
        __nv_bfloat16 lo = __float2bfloat16_rn(wv - __bfloat162float(hi));
        unsigned off = (unsigned)row * 1024u +
                       ((((unsigned)k >> 3) ^ (unsigned)(row & 7)) << 4) +
                       (unsigned)(k & 7) * 2u;
        *(__nv_bfloat16*)(smem + WH_OFF + off) = hi;
        *(__nv_bfloat16*)(smem + WL_OFF + off) = lo;
    }

    const int en = tid >> 2;
    const int em = (tid & 3) * 8;
    float bhv[8];
    *(float4*)&bhv[0] = *(const float4*)&bh[r0 + em];
    *(float4*)&bhv[4] = *(const float4*)&bh[r0 + em + 4];
    __syncthreads();

    const int kw    = w * 128;
    const int quad  = l >> 3, li = l & 7;
    const int a_row = ((quad & 1) << 3) + li;
    const int a_kof = (quad >> 1) << 3;
    const int b_i   = l & 7;
    const int b_half = (l >> 3) & 1;

    for (int t = 0; t < T_; ++t) {
        const unsigned short* sHi =
            (t == 0) ? g_h0hi : g_Hhi + (size_t)(t - 1) * B_ * H_;
        const unsigned short* sLo =
            (t == 0) ? g_h0lo : g_Hlo + (size_t)(t - 1) * B_ * H_;
        #pragma unroll
        for (int j = 0; j < 16; ++j) {
            int i = tid + j * 128;
            int row = i >> 6, c = i & 63;
            cp16(sb + HH_OFF + (unsigned)row * 1024u + ((unsigned)(c ^ (row & 7)) << 4),
                 sHi + (size_t)(c0 + row) * H_ + c * 8);
        }
        cp_commit();
        #pragma unroll
        for (int j = 0; j < 16; ++j) {
            int i = tid + j * 128;
            int row = i >> 6, c = i & 63;
            cp16(sb + HL_OFF + (unsigned)row * 1024u + ((unsigned)(c ^ (row & 7)) << 4),
                 sLo + (size_t)(c0 + row) * H_ + c * 8);
        }
        cp_commit();

        int x = inp[t * B_ + c0 + en];
        float uv[8];
        *(float4*)&uv[0] = *(const float4*)&g_Ut[(size_t)x * H_ + r0 + em];
        *(float4*)&uv[4] = *(const float4*)&g_Ut[(size_t)x * H_ + r0 + em + 4];

        float acc[2][4][4];
        #pragma unroll
        for (int mt = 0; mt < 2; ++mt)
            #pragma unroll
            for (int nt = 0; nt < 4; ++nt)
                #pragma unroll
                for (int q = 0; q < 4; ++q) acc[mt][nt][q] = 0.f;

        cp_wait<1>();
        __syncthreads();

        // phase 1: Wh*hh + Wl*hh
        #pragma unroll
        for (int ks = 0; ks < 8; ++ks) {
            const int kk = kw + ks * 16;
            unsigned bfr[4][2];
            #pragma unroll
            for (int nt = 0; nt < 4; ++nt) {
                int rn = nt * 8 + b_i;
                unsigned ba = sb + HH_OFF + (unsigned)rn * 1024u +
                    ((((unsigned)(kk + b_half * 8) >> 3) ^ (unsigned)(rn & 7)) << 4);
                ldsm_x2(bfr[nt], ba);
            }
            #pragma unroll
            for (int mt = 0; mt < 2; ++mt) {
                int row = mt * 16 + a_row;
                unsigned afr[4];
                unsigned aa = sb + WH_OFF + (unsigned)row * 1024u +
                    ((((unsigned)(kk + a_kof) >> 3) ^ (unsigned)(row & 7)) << 4);
                ldsm_x4(afr, aa);
                #pragma unroll
                for (int nt = 0; nt < 4; ++nt) mma_bf16(acc[mt][nt], afr, bfr[nt]);
            }
            #pragma unroll
            for (int mt = 0; mt < 2; ++mt) {
                int row = mt * 16 + a_row;
                unsigned afr[4];
                unsigned aa = sb + WL_OFF + (unsigned)row * 1024u +
                    ((((unsigned)(kk + a_kof) >> 3) ^ (unsigned)(row & 7)) << 4);
                ldsm_x4(afr, aa);
                #pragma unroll
                for (int nt = 0; nt < 4; ++nt) mma_bf16(acc[mt][nt], afr, bfr[nt]);
            }
        }

        cp_wait<0>();
        __syncthreads();

        // phase 2: Wh*hl
        #pragma unroll
        for (int ks = 0; ks < 8; ++ks) {
            const int kk = kw + ks * 16;
            unsigned bfr[4][2];
            #pragma unroll
            for (int nt = 0; nt < 4; ++nt) {
                int rn = nt * 8 + b_i;
                unsigned ba = sb + HL_OFF + (unsigned)rn * 1024u +
                    ((((unsigned)(kk + b_half * 8) >> 3) ^ (unsigned)(rn & 7)) << 4);
                ldsm_x2(bfr[nt], ba);
            }
            #pragma unroll
            for (int mt = 0; mt < 2; ++mt) {
                int row = mt * 16 + a_row;
                unsigned afr[4];
                unsigned aa = sb + WH_OFF + (unsigned)row * 1024u +
                    ((((unsigned)(kk + a_kof) >> 3) ^ (unsigned)(row & 7)) << 4);
                ldsm_x4(afr, aa);
                #pragma unroll
                for (int nt = 0; nt < 4; ++nt) mma_bf16(acc[mt][nt], afr, bfr[nt]);
            }
        }

        // cross-warp k reduction
        {
            int g = l >> 2, q = l & 3;
            #pragma unroll
            for (int mt = 0; mt < 2; ++mt)
                #pragma unroll
                for (int nt = 0; nt < 4; ++nt) {
                    int m = mt * 16 + g, n = nt * 8 + 2 * q;
                    RED[(w * 32 + m) * 33 + n]         = acc[mt][nt][0];
                    RED[(w * 32 + m) * 33 + n + 1]     = acc[mt][nt][1];
                    RED[(w * 32 + m + 8) * 33 + n]     = acc[mt][nt][2];
                    RED[(w * 32 + m + 8) * 33 + n + 1] = acc[mt][nt][3];
                }
        }
        __syncthreads();

        // epilogue: tanh + store planes only
        unsigned short* pHi = g_Hhi + (size_t)t * B_ * H_;
        unsigned short* pLo = g_Hlo + (size_t)t * B_ * H_;
        unsigned short hu[8], lu[8];
        #pragma unroll
        for (int r = 0; r < 8; ++r) {
            int m = em + r;
            float s = RED[(0 * 32 + m) * 33 + en] + RED[(1 * 32 + m) * 33 + en] +
                      RED[(2 * 32 + m) * 33 + en] + RED[(3 * 32 + m) * 33 + en];
            float hv = fast_tanh(s + uv[r] + bhv[r]);
            __nv_bfloat16 hi = __float2bfloat16_rn(hv);
            __nv_bfloat16 lo = __float2bfloat16_rn(hv - __bfloat162float(hi));
            hu[r] = __bfloat16_as_ushort(hi);
            lu[r] = __bfloat16_as_ushort(lo);
        }
        size_t ofs = (size_t)(c0 + en) * H_ + r0 + em;
        *(uint4*)&pHi[ofs] = *(uint4*)&hu[0];
        *(uint4*)&pLo[ofs] = *(uint4*)&lu[0];

        group_barrier(bc);
    }
}

// ---------------- Phase B: tensor-core logits GEMM ----------------
// CTA: 128 threads (4 warps), tile 64b x 64o, K chunks of 128, double-buffered.
// smem per buffer: Ah|Al|Vh|Vl each [64][128] bf16 (16KB) -> 64KB; x2 = 128KB
#define PB_AH 0
#define PB_AL 16384
#define PB_VH 32768
#define PB_VL 49152
#define PB_BUF 65536
#define SMEM_B_BYTES (2 * PB_BUF)

__global__ void __launch_bounds__(128, 1)
rnn_logits_mma(const float* __restrict__ by, float* __restrict__ out)
{
    extern __shared__ char smem[];
    const unsigned sb = smem_u32(smem);

    const int t  = blockIdx.z;
    const int ob = blockIdx.x * 64;
    const int bb = blockIdx.y * 64;
    const int tid = threadIdx.x;
    const int w = tid >> 5;
    const int l = tid & 31;
    const int wb = (w >> 1) * 32;     // warp b-offset (2 groups)
    const int wo = (w & 1) * 32;      // warp o-offset (2 groups)

    const int quad  = l >> 3, li = l & 7;
    const int a_row = ((quad & 1) << 3) + li;
    const int a_kof = (quad >> 1) << 3;
    const int b_i   = l & 7;
    const int b_half = (l >> 3) & 1;

    const unsigned short* Ahi = g_Hhi + ((size_t)t * B_ + bb) * H_;
    const unsigned short* Alo = g_Hlo + ((size_t)t * B_ + bb) * H_;

    // fill chunk c (k = c*128 .. +128) into buffer buf
    auto fill = [&](int c, unsigned buf) {
        const int kc = c * 128;
        #pragma unroll
        for (int j = 0; j < 8; ++j) {
            int i = tid + j * 128;          // 0..1023
            int row = i >> 4, cc = i & 15;
            unsigned dst = (unsigned)(row * 256) + ((unsigned)(cc ^ (row & 7)) << 4);
            size_t srcA = (size_t)row * H_ + kc + cc * 8;
            cp16(sb + buf + PB_AH + dst, Ahi + srcA);
            cp16(sb + buf + PB_AL + dst, Alo + srcA);
            size_t srcV = (size_t)(ob + row) * H_ + kc + cc * 8;
            cp16(sb + buf + PB_VH + dst, g_Vhi + srcV);
            cp16(sb + buf + PB_VL + dst, g_Vlo + srcV);
        }
    };

    float acc[2][4][4];
    #pragma unroll
    for (int mt = 0; mt < 2; ++mt)
        #pragma unroll
        for (int nt = 0; nt < 4; ++nt)
            #pragma unroll
            for (int q = 0; q < 4; ++q) acc[mt][nt][q] = 0.f;

    fill(0, 0);
    cp_commit();

    for (int c = 0; c < 4; ++c) {
        if (c < 3) fill(c + 1, (unsigned)((c + 1) & 1) * PB_BUF);
        cp_commit();
        cp_wait<1>();
        __syncthreads();

        const unsigned buf = sb + (unsigned)(c & 1) * PB_BUF;
        #pragma unroll
        for (int ks = 0; ks < 8; ++ks) {
            const int kk = ks * 16;
            unsigned vh[4][2], vl[4][2];
            #pragma unroll
            for (int nt = 0; nt < 4; ++nt) {
                int rn = wo + nt * 8 + b_i;
                unsigned boff = (unsigned)(rn * 256) +
                    ((((unsigned)(kk + b_half * 8) >> 3) ^ (unsigned)(rn & 7)) << 4);
                ldsm_x2(vh[nt], buf + PB_VH + boff);
                ldsm_x2(vl[nt], buf + PB_VL + boff);
            }
            #pragma unroll
            for (int mt = 0; mt < 2; ++mt) {
                int row = wb + mt * 16 + a_row;
                unsigned aoff = (unsigned)(row * 256) +
                    ((((unsigned)(kk + a_kof) >> 3) ^ (unsigned)(row & 7)) << 4);
                unsigned ah[4], al[4];
                ldsm_x4(ah, buf + PB_AH + aoff);
                ldsm_x4(al, buf + PB_AL + aoff);
                #pragma unroll
                for (int nt = 0; nt < 4; ++nt) {
                    mma_bf16(acc[mt][nt], ah, vh[nt]);   // hh*Vh
                    mma_bf16(acc[mt][nt], al, vh[nt]);   // hl*Vh
                    mma_bf16(acc[mt][nt], ah, vl[nt]);   // hh*Vl
                }
            }
        }
        __syncthreads();
    }

    // epilogue: d frag thread map: rows (l>>2), (l>>2)+8; cols 2*(l&3), +1
    const int fr = l >> 2, fc = 2 * (l & 3);
    #pragma unroll
    for (int nt = 0; nt < 4; ++nt) {
        int col = ob + wo + nt * 8 + fc;
        float2 b2 = *(const float2*)&by[col];
        #pragma unroll
        for (int mt = 0; mt < 2; ++mt) {
            int r0w = bb + wb + mt * 16 + fr;
            float2 v0 = make_float2(acc[mt][nt][0] + b2.x, acc[mt][nt][1] + b2.y);
            float2 v1 = make_float2(acc[mt][nt][2] + b2.x, acc[mt][nt][3] + b2.y);
            *(float2*)&out[((size_t)t * B_ + r0w) * O_ + col]     = v0;
            *(float2*)&out[((size_t)t * B_ + r0w + 8) * O_ + col] = v1;
        }
    }
}

// Optional hT (H,B) appended after logits: reconstruct from planes
__global__ void copy_hT_kernel(float* __restrict__ out) {
    int h = blockIdx.x;      // 512
    int b = threadIdx.x;     // 256
    size_t ofs = (size_t)(T_ - 1) * B_ * H_ + (size_t)b * H_ + h;
    out[(size_t)h * B_ + b] = bf16hl(g_Hhi[ofs]) + bf16hl(g_Hlo[ofs]);
}

extern "C" void kernel_launch(void* const* d_in, const int* in_sizes, int n_in,
                              void* d_out, int out_size) {
    const int*   inp = (const int*)d_in[0];
    const float* h0  = (const float*)d_in[1];
    const float* U   = (const float*)d_in[2];
    const float* W   = (const float*)d_in[3];
    const float* Vm  = (const float*)d_in[4];
    const float* bh  = (const float*)d_in[5];
    const float* by  = (const float*)d_in[6];
    float* out = (float*)d_out;

    cudaFuncSetAttribute(rnn_recur_mma,
                         cudaFuncAttributeMaxDynamicSharedMemorySize,
                         (int)SMEM_A_BYTES);
    cudaFuncSetAttribute(rnn_logits_mma,
                         cudaFuncAttributeMaxDynamicSharedMemorySize,
                         (int)SMEM_B_BYTES);

    prep_Ut<<<D_, H_>>>(U);
    prep_h0planes<<<B_, H_>>>(h0);
    prep_Vplanes<<<O_, H_>>>(Vm);

    rnn_recur_mma<<<NBLK_A, 128, SMEM_A_BYTES>>>(inp, W, bh);

    dim3 gridB(O_ / 64, B_ / 64, T_);
    rnn_logits_mma<<<gridB, 128, SMEM_B_BYTES>>>(by, out);

    if (out_size >= T_ * B_ * O_ + H_ * B_) {
        copy_hT_kernel<<<H_, B_>>>(out + (size_t)T_ * B_ * O_);
    }
}

// round 9
// speedup vs baseline: 2.4107x; 1.1222x over previous
#include <cuda_runtime.h>
#include <cuda_bf16.h>
#include <math.h>
#include <stdint.h>

// Problem dims
#define T_ 1024
#define B_ 256
#define D_ 256
#define H_ 512
#define O_ 256

#define NBLK_A 128
#define MB 32
#define NB 32

typedef unsigned long long ull;

// bf16 hi/lo planes of hidden history, (t, b, h) layout, h contiguous
__device__ unsigned short g_Hhi[(size_t)T_ * B_ * H_];
__device__ unsigned short g_Hlo[(size_t)T_ * B_ * H_];
__device__ unsigned short g_h0hi[B_ * H_];
__device__ unsigned short g_h0lo[B_ * H_];
__device__ unsigned short g_Vhi[O_ * H_];
__device__ unsigned short g_Vlo[O_ * H_];
__device__ float          g_Ut[D_ * H_];      // U transposed (D, H)

// Per-column-group barriers (8 groups x 16 CTAs), one cache line each
__device__ unsigned g_cg_cnt[8 * 32];
__device__ unsigned g_cg_gen[8 * 32];

// ---------------- helpers ----------------
__device__ __forceinline__ float bf16hl(unsigned short u) {
    return __uint_as_float((unsigned)u << 16);
}
__device__ __forceinline__ unsigned smem_u32(const void* p) {
    return (unsigned)__cvta_generic_to_shared(p);
}
__device__ __forceinline__ void cp16(unsigned dst, const void* src) {
    asm volatile("cp.async.cg.shared.global [%0], [%1], 16;\n" ::"r"(dst), "l"(src));
}
__device__ __forceinline__ void cp_commit() {
    asm volatile("cp.async.commit_group;\n");
}
template <int N> __device__ __forceinline__ void cp_wait() {
    asm volatile("cp.async.wait_group %0;\n" ::"n"(N));
}
__device__ __forceinline__ float fast_tanh(float x) {
    float e, r;
    asm("ex2.approx.f32 %0, %1;" : "=f"(e) : "f"(x * 2.8853900817779268f));
    asm("rcp.approx.f32 %0, %1;" : "=f"(r) : "f"(e + 1.0f));
    return fmaf(-2.0f, r, 1.0f);
}
__device__ __forceinline__ void ldsm_x4(unsigned* r, unsigned addr) {
    asm volatile("ldmatrix.sync.aligned.m8n8.x4.shared.b16 {%0,%1,%2,%3}, [%4];"
                 : "=r"(r[0]), "=r"(r[1]), "=r"(r[2]), "=r"(r[3]) : "r"(addr));
}
__device__ __forceinline__ void ldsm_x2(unsigned* r, unsigned addr) {
    asm volatile("ldmatrix.sync.aligned.m8n8.x2.shared.b16 {%0,%1}, [%2];"
                 : "=r"(r[0]), "=r"(r[1]) : "r"(addr));
}
__device__ __forceinline__ void mma_bf16(float* d, const unsigned* a, const unsigned* b) {
    asm volatile(
        "mma.sync.aligned.m16n8k16.row.col.f32.bf16.bf16.f32 "
        "{%0,%1,%2,%3}, {%4,%5,%6,%7}, {%8,%9}, {%0,%1,%2,%3};"
        : "+f"(d[0]), "+f"(d[1]), "+f"(d[2]), "+f"(d[3])
        : "r"(a[0]), "r"(a[1]), "r"(a[2]), "r"(a[3]), "r"(b[0]), "r"(b[1]));
}

// Column-group barrier, fence-free: release-atomic arrival / acquire spin.
// Preceded by __syncthreads() so tid0's release publishes all threads' stores.
__device__ __forceinline__ void group_barrier(int bc) {
    __syncthreads();
    if (threadIdx.x == 0) {
        unsigned* cnt = &g_cg_cnt[bc * 32];
        unsigned* gen = &g_cg_gen[bc * 32];
        unsigned my;
        asm volatile("ld.relaxed.gpu.u32 %0, [%1];" : "=r"(my) : "l"(gen) : "memory");
        unsigned old;
        asm volatile("atom.add.release.gpu.u32 %0, [%1], %2;"
                     : "=r"(old) : "l"(cnt), "r"(1u) : "memory");
        if (old == 15u) {
            asm volatile("st.relaxed.gpu.u32 [%0], %1;" :: "l"(cnt), "r"(0u) : "memory");
            asm volatile("st.release.gpu.u32 [%0], %1;" :: "l"(gen), "r"(my + 1u) : "memory");
        } else {
            unsigned g;
            do {
                asm volatile("ld.acquire.gpu.u32 %0, [%1];" : "=r"(g) : "l"(gen) : "memory");
            } while (g == my);
        }
    }
    __syncthreads();
}

// ---------------- prep kernels ----------------
__global__ void prep_Ut(const float* __restrict__ U) {
    int d = blockIdx.x, h = threadIdx.x;
    g_Ut[(size_t)d * H_ + h] = U[(size_t)h * D_ + d];
}
__global__ void prep_h0planes(const float* __restrict__ h0) {
    int b = blockIdx.x, h = threadIdx.x;
    float v = h0[(size_t)h * B_ + b];
    __nv_bfloat16 hi = __float2bfloat16_rn(v);
    __nv_bfloat16 lo = __float2bfloat16_rn(v - __bfloat162float(hi));
    g_h0hi[(size_t)b * H_ + h] = __bfloat16_as_ushort(hi);
    g_h0lo[(size_t)b * H_ + h] = __bfloat16_as_ushort(lo);
}
__global__ void prep_Vplanes(const float* __restrict__ Vm) {
    int o = blockIdx.x, h = threadIdx.x;
    float v = Vm[(size_t)o * H_ + h];
    __nv_bfloat16 hi = __float2bfloat16_rn(v);
    __nv_bfloat16 lo = __float2bfloat16_rn(v - __bfloat162float(hi));
    g_Vhi[(size_t)o * H_ + h] = __bfloat16_as_ushort(hi);
    g_Vlo[(size_t)o * H_ + h] = __bfloat16_as_ushort(lo);
}

// ---------------- Phase A: warp-MMA recurrence, 8 warps k-split ----------
#define WH_OFF 0
#define WL_OFF 32768
#define HH_OFF 65536
#define HL_OFF 98304
#define RED_OFF 131072
#define SMEM_A_BYTES (RED_OFF + 8 * 32 * 33 * 4)

__global__ void __launch_bounds__(256, 1)
rnn_recur_mma(const int* __restrict__ inp, const float* __restrict__ W,
              const float* __restrict__ bh)
{
    extern __shared__ char smem[];
    const unsigned sb = smem_u32(smem);
    float* RED = (float*)(smem + RED_OFF);

    const int tid = threadIdx.x;
    const int w   = tid >> 5;           // 8 warps
    const int l   = tid & 31;
    const int bid = blockIdx.x;
    const int r0 = (bid >> 3) * MB;
    const int bc = bid & 7;
    const int c0 = bc * NB;

    // one-time: split W slab (32 x 512) into Wh/Wl bf16, swizzled smem
    for (int i = tid; i < MB * H_; i += 256) {
        int row = i >> 9, k = i & 511;
        float wv = W[(size_t)(r0 + row) * H_ + k];
        __nv_bfloat16 hi = __float2bfloat16_rn(wv);
        __nv_bfloat16 lo = __float2bfloat16_rn(wv - __bfloat162float(hi));
        unsigned off = (unsigned)row * 1024u +
                       ((((unsigned)k >> 3) ^ (unsigned)(row & 7)) << 4) +
                       (unsigned)(k & 7) * 2u;
        *(__nv_bfloat16*)(smem + WH_OFF + off) = hi;
        *(__nv_bfloat16*)(smem + WL_OFF + off) = lo;
    }

    // epilogue ownership: col en (0..31), rows em..em+3
    const int en = tid >> 3;
    const int em = (tid & 7) * 4;
    float4 bhv = *(const float4*)&bh[r0 + em];
    __syncthreads();

    // ldmatrix lane geometry (warp owns k quarter-of-half: 64 wide)
    const int kw    = w * 64;
    const int quad  = l >> 3, li = l & 7;
    const int a_row = ((quad & 1) << 3) + li;
    const int a_kof = (quad >> 1) << 3;
    const int b_i   = l & 7;
    const int b_half = (l >> 3) & 1;

    for (int t = 0; t < T_; ++t) {
        const unsigned short* sHi =
            (t == 0) ? g_h0hi : g_Hhi + (size_t)(t - 1) * B_ * H_;
        const unsigned short* sLo =
            (t == 0) ? g_h0lo : g_Hlo + (size_t)(t - 1) * B_ * H_;
        #pragma unroll
        for (int j = 0; j < 8; ++j) {
            int i = tid + j * 256;               // 0..2047
            int row = i >> 6, c = i & 63;
            cp16(sb + HH_OFF + (unsigned)row * 1024u + ((unsigned)(c ^ (row & 7)) << 4),
                 sHi + (size_t)(c0 + row) * H_ + c * 8);
        }
        cp_commit();
        #pragma unroll
        for (int j = 0; j < 8; ++j) {
            int i = tid + j * 256;
            int row = i >> 6, c = i & 63;
            cp16(sb + HL_OFF + (unsigned)row * 1024u + ((unsigned)(c ^ (row & 7)) << 4),
                 sLo + (size_t)(c0 + row) * H_ + c * 8);
        }
        cp_commit();

        // U gather (overlaps cp.async)
        int x = inp[t * B_ + c0 + en];
        float4 uv = *(const float4*)&g_Ut[(size_t)x * H_ + r0 + em];

        float acc[2][4][4];
        #pragma unroll
        for (int mt = 0; mt < 2; ++mt)
            #pragma unroll
            for (int nt = 0; nt < 4; ++nt)
                #pragma unroll
                for (int q = 0; q < 4; ++q) acc[mt][nt][q] = 0.f;

        cp_wait<1>();
        __syncthreads();

        // phase 1: Wh*hh + Wl*hh over this warp's 64-wide k slice
        #pragma unroll
        for (int ks = 0; ks < 4; ++ks) {
            const int kk = kw + ks * 16;
            unsigned bfr[4][2];
            #pragma unroll
            for (int nt = 0; nt < 4; ++nt) {
                int rn = nt * 8 + b_i;
                unsigned ba = sb + HH_OFF + (unsigned)rn * 1024u +
                    ((((unsigned)(kk + b_half * 8) >> 3) ^ (unsigned)(rn & 7)) << 4);
                ldsm_x2(bfr[nt], ba);
            }
            #pragma unroll
            for (int mt = 0; mt < 2; ++mt) {
                int row = mt * 16 + a_row;
                unsigned afr[4];
                unsigned aa = sb + WH_OFF + (unsigned)row * 1024u +
                    ((((unsigned)(kk + a_kof) >> 3) ^ (unsigned)(row & 7)) << 4);
                ldsm_x4(afr, aa);
                #pragma unroll
                for (int nt = 0; nt < 4; ++nt) mma_bf16(acc[mt][nt], afr, bfr[nt]);
            }
            #pragma unroll
            for (int mt = 0; mt < 2; ++mt) {
                int row = mt * 16 + a_row;
                unsigned afr[4];
                unsigned aa = sb + WL_OFF + (unsigned)row * 1024u +
                    ((((unsigned)(kk + a_kof) >> 3) ^ (unsigned)(row & 7)) << 4);
                ldsm_x4(afr, aa);
                #pragma unroll
                for (int nt = 0; nt < 4; ++nt) mma_bf16(acc[mt][nt], afr, bfr[nt]);
            }
        }

        cp_wait<0>();
        __syncthreads();

        // phase 2: Wh*hl
        #pragma unroll
        for (int ks = 0; ks < 4; ++ks) {
            const int kk = kw + ks * 16;
            unsigned bfr[4][2];
            #pragma unroll
            for (int nt = 0; nt < 4; ++nt) {
                int rn = nt * 8 + b_i;
                unsigned ba = sb + HL_OFF + (unsigned)rn * 1024u +
                    ((((unsigned)(kk + b_half * 8) >> 3) ^ (unsigned)(rn & 7)) << 4);
                ldsm_x2(bfr[nt], ba);
            }
            #pragma unroll
            for (int mt = 0; mt < 2; ++mt) {
                int row = mt * 16 + a_row;
                unsigned afr[4];
                unsigned aa = sb + WH_OFF + (unsigned)row * 1024u +
                    ((((unsigned)(kk + a_kof) >> 3) ^ (unsigned)(row & 7)) << 4);
                ldsm_x4(afr, aa);
                #pragma unroll
                for (int nt = 0; nt < 4; ++nt) mma_bf16(acc[mt][nt], afr, bfr[nt]);
            }
        }

        // cross-warp k reduction (8 partials)
        {
            int g = l >> 2, q = l & 3;
            #pragma unroll
            for (int mt = 0; mt < 2; ++mt)
                #pragma unroll
                for (int nt = 0; nt < 4; ++nt) {
                    int m = mt * 16 + g, n = nt * 8 + 2 * q;
                    RED[(w * 32 + m) * 33 + n]         = acc[mt][nt][0];
                    RED[(w * 32 + m) * 33 + n + 1]     = acc[mt][nt][1];
                    RED[(w * 32 + m + 8) * 33 + n]     = acc[mt][nt][2];
                    RED[(w * 32 + m + 8) * 33 + n + 1] = acc[mt][nt][3];
                }
        }
        __syncthreads();

        // epilogue: sum 8 partials + U + bias, tanh, store planes
        unsigned short* pHi = g_Hhi + (size_t)t * B_ * H_;
        unsigned short* pLo = g_Hlo + (size_t)t * B_ * H_;
        unsigned short hu[4], lu[4];
        const float* uvp = &uv.x;
        const float* bhp = &bhv.x;
        #pragma unroll
        for (int r = 0; r < 4; ++r) {
            int m = em + r;
            float s = 0.f;
            #pragma unroll
            for (int ww = 0; ww < 8; ++ww)
                s += RED[(ww * 32 + m) * 33 + en];
            float hv = fast_tanh(s + uvp[r] + bhp[r]);
            __nv_bfloat16 hi = __float2bfloat16_rn(hv);
            __nv_bfloat16 lo = __float2bfloat16_rn(hv - __bfloat162float(hi));
            hu[r] = __bfloat16_as_ushort(hi);
            lu[r] = __bfloat16_as_ushort(lo);
        }
        size_t ofs = (size_t)(c0 + en) * H_ + r0 + em;
        *(uint2*)&pHi[ofs] = *(uint2*)&hu[0];
        *(uint2*)&pLo[ofs] = *(uint2*)&lu[0];

        group_barrier(bc);
    }
}

// ---------------- Phase B: tensor-core logits GEMM (proven round-8) --------
#define PB_AH 0
#define PB_AL 16384
#define PB_VH 32768
#define PB_VL 49152
#define PB_BUF 65536
#define SMEM_B_BYTES (2 * PB_BUF)

__global__ void __launch_bounds__(128, 1)
rnn_logits_mma(const float* __restrict__ by, float* __restrict__ out)
{
    extern __shared__ char smem[];
    const unsigned sb = smem_u32(smem);

    const int t  = blockIdx.z;
    const int ob = blockIdx.x * 64;
    const int bb = blockIdx.y * 64;
    const int tid = threadIdx.x;
    const int w = tid >> 5;
    const int l = tid & 31;
    const int wb = (w >> 1) * 32;
    const int wo = (w & 1) * 32;

    const int quad  = l >> 3, li = l & 7;
    const int a_row = ((quad & 1) << 3) + li;
    const int a_kof = (quad >> 1) << 3;
    const int b_i   = l & 7;
    const int b_half = (l >> 3) & 1;

    const unsigned short* Ahi = g_Hhi + ((size_t)t * B_ + bb) * H_;
    const unsigned short* Alo = g_Hlo + ((size_t)t * B_ + bb) * H_;

    auto fill = [&](int c, unsigned buf) {
        const int kc = c * 128;
        #pragma unroll
        for (int j = 0; j < 8; ++j) {
            int i = tid + j * 128;
            int row = i >> 4, cc = i & 15;
            unsigned dst = (unsigned)(row * 256) + ((unsigned)(cc ^ (row & 7)) << 4);
            size_t srcA = (size_t)row * H_ + kc + cc * 8;
            cp16(sb + buf + PB_AH + dst, Ahi + srcA);
            cp16(sb + buf + PB_AL + dst, Alo + srcA);
            size_t srcV = (size_t)(ob + row) * H_ + kc + cc * 8;
            cp16(sb + buf + PB_VH + dst, g_Vhi + srcV);
            cp16(sb + buf + PB_VL + dst, g_Vlo + srcV);
        }
    };

    float acc[2][4][4];
    #pragma unroll
    for (int mt = 0; mt < 2; ++mt)
        #pragma unroll
        for (int nt = 0; nt < 4; ++nt)
            #pragma unroll
            for (int q = 0; q < 4; ++q) acc[mt][nt][q] = 0.f;

    fill(0, 0);
    cp_commit();

    for (int c = 0; c < 4; ++c) {
        if (c < 3) fill(c + 1, (unsigned)((c + 1) & 1) * PB_BUF);
        cp_commit();
        cp_wait<1>();
        __syncthreads();

        const unsigned buf = sb + (unsigned)(c & 1) * PB_BUF;
        #pragma unroll
        for (int ks = 0; ks < 8; ++ks) {
            const int kk = ks * 16;
            unsigned vh[4][2], vl[4][2];
            #pragma unroll
            for (int nt = 0; nt < 4; ++nt) {
                int rn = wo + nt * 8 + b_i;
                unsigned boff = (unsigned)(rn * 256) +
                    ((((unsigned)(kk + b_half * 8) >> 3) ^ (unsigned)(rn & 7)) << 4);
                ldsm_x2(vh[nt], buf + PB_VH + boff);
                ldsm_x2(vl[nt], buf + PB_VL + boff);
            }
            #pragma unroll
            for (int mt = 0; mt < 2; ++mt) {
                int row = wb + mt * 16 + a_row;
                unsigned aoff = (unsigned)(row * 256) +
                    ((((unsigned)(kk + a_kof) >> 3) ^ (unsigned)(row & 7)) << 4);
                unsigned ah[4], al[4];
                ldsm_x4(ah, buf + PB_AH + aoff);
                ldsm_x4(al, buf + PB_AL + aoff);
                #pragma unroll
                for (int nt = 0; nt < 4; ++nt) {
                    mma_bf16(acc[mt][nt], ah, vh[nt]);
                    mma_bf16(acc[mt][nt], al, vh[nt]);
                    mma_bf16(acc[mt][nt], ah, vl[nt]);
                }
            }
        }
        __syncthreads();
    }

    const int fr = l >> 2, fc = 2 * (l & 3);
    #pragma unroll
    for (int nt = 0; nt < 4; ++nt) {
        int col = ob + wo + nt * 8 + fc;
        float2 b2 = *(const float2*)&by[col];
        #pragma unroll
        for (int mt = 0; mt < 2; ++mt) {
            int r0w = bb + wb + mt * 16 + fr;
            float2 v0 = make_float2(acc[mt][nt][0] + b2.x, acc[mt][nt][1] + b2.y);
            float2 v1 = make_float2(acc[mt][nt][2] + b2.x, acc[mt][nt][3] + b2.y);
            *(float2*)&out[((size_t)t * B_ + r0w) * O_ + col]     = v0;
            *(float2*)&out[((size_t)t * B_ + r0w + 8) * O_ + col] = v1;
        }
    }
}

// Optional hT (H,B) appended after logits: reconstruct from planes
__global__ void copy_hT_kernel(float* __restrict__ out) {
    int h = blockIdx.x;
    int b = threadIdx.x;
    size_t ofs = (size_t)(T_ - 1) * B_ * H_ + (size_t)b * H_ + h;
    out[(size_t)h * B_ + b] = bf16hl(g_Hhi[ofs]) + bf16hl(g_Hlo[ofs]);
}

extern "C" void kernel_launch(void* const* d_in, const int* in_sizes, int n_in,
                              void* d_out, int out_size) {
    const int*   inp = (const int*)d_in[0];
    const float* h0  = (const float*)d_in[1];
    const float* U   = (const float*)d_in[2];
    const float* W   = (const float*)d_in[3];
    const float* Vm  = (const float*)d_in[4];
    const float* bh  = (const float*)d_in[5];
    const float* by  = (const float*)d_in[6];
    float* out = (float*)d_out;

    cudaFuncSetAttribute(rnn_recur_mma,
                         cudaFuncAttributeMaxDynamicSharedMemorySize,
                         (int)SMEM_A_BYTES);
    cudaFuncSetAttribute(rnn_logits_mma,
                         cudaFuncAttributeMaxDynamicSharedMemorySize,
                         (int)SMEM_B_BYTES);

    prep_Ut<<<D_, H_>>>(U);
    prep_h0planes<<<B_, H_>>>(h0);
    prep_Vplanes<<<O_, H_>>>(Vm);

    rnn_recur_mma<<<NBLK_A, 256, SMEM_A_BYTES>>>(inp, W, bh);

    dim3 gridB(O_ / 64, B_ / 64, T_);
    rnn_logits_mma<<<gridB, 128, SMEM_B_BYTES>>>(by, out);

    if (out_size >= T_ * B_ * O_ + H_ * B_) {
        copy_hT_kernel<<<H_, B_>>>(out + (size_t)T_ * B_ * O_);
    }
}